// round 17
// baseline (speedup 1.0000x reference)
#include <cuda_runtime.h>
#include <cuda_bf16.h>
#include <cstdint>

// Problem dims (fixed by the reference)
#define BB 2
#define LL 2048
#define DD 1024
#define HH 16
#define DH 64
#define MTOT (BB*LL)        // 4096
#define KP   (DD/2)         // 512 bf16-pairs along K

typedef unsigned long long ull;

// ---------------- mma helpers (sm_80+ base target) ----------------
__device__ __forceinline__ uint32_t tf32bits(float f) {
    uint32_t r; asm("cvt.rna.tf32.f32 %0, %1;" : "=r"(r) : "f"(f)); return r;
}
__device__ __forceinline__ float tf32f(float f) {
    return __uint_as_float(tf32bits(f));
}
__device__ __forceinline__ void mma_tf32(float c[4], const uint32_t a[4],
                                         uint32_t b0, uint32_t b1) {
    asm volatile(
        "mma.sync.aligned.m16n8k8.row.col.f32.tf32.tf32.f32 "
        "{%0,%1,%2,%3}, {%4,%5,%6,%7}, {%8,%9}, {%0,%1,%2,%3};"
        : "+f"(c[0]), "+f"(c[1]), "+f"(c[2]), "+f"(c[3])
        : "r"(a[0]), "r"(a[1]), "r"(a[2]), "r"(a[3]), "r"(b0), "r"(b1));
}
__device__ __forceinline__ void mma_bf16(float c[4], const uint32_t a[4],
                                         uint32_t b0, uint32_t b1) {
    asm volatile(
        "mma.sync.aligned.m16n8k16.row.col.f32.bf16.bf16.f32 "
        "{%0,%1,%2,%3}, {%4,%5,%6,%7}, {%8,%9}, {%0,%1,%2,%3};"
        : "+f"(c[0]), "+f"(c[1]), "+f"(c[2]), "+f"(c[3])
        : "r"(a[0]), "r"(a[1]), "r"(a[2]), "r"(a[3]), "r"(b0), "r"(b1));
}
__device__ __forceinline__ uint32_t smem_u32(const void* p) {
    uint32_t a;
    asm("{ .reg .u64 t; cvta.to.shared.u64 t, %1; cvt.u32.u64 %0, t; }" : "=r"(a) : "l"(p));
    return a;
}
__device__ __forceinline__ void cp16(uint32_t dst, const void* src) {
    asm volatile("cp.async.ca.shared.global [%0], [%1], 16;" :: "r"(dst), "l"(src) : "memory");
}
#define CP_COMMIT() asm volatile("cp.async.commit_group;" ::: "memory")
#define CP_WAIT(n)  asm volatile("cp.async.wait_group %0;" :: "n"(n) : "memory")

// -------- scratch (static device globals; no allocation allowed) --------
__device__ float g_qkv[(size_t)MTOT * 3 * DD];          // (B*L, 3072)
__device__ float g_q[(size_t)BB * HH * LL * DH];        // (b,h,l,d)
__device__ float g_k[(size_t)BB * HH * LL * DH];        // tf32-rounded
__device__ float g_v[(size_t)BB * HH * LL * DH];        // TRANSPOSED (b,h,d,l), tf32-rounded
// split-bf16 packed pair arrays (u32 = two bf16), PRE-PERMUTED:
// within each group of 8 u32 along K, pair j sits at slot (j%4)*2 + j/4.
__device__ uint32_t g_xb[(size_t)MTOT * KP];
__device__ uint32_t g_xs[(size_t)MTOT * KP];
__device__ uint32_t g_wqb[(size_t)3 * DD * KP];
__device__ uint32_t g_wqs[(size_t)3 * DD * KP];
__device__ uint32_t g_wpb[(size_t)DD * KP];
__device__ uint32_t g_wps[(size_t)DD * KP];
__device__ uint32_t g_ob[(size_t)MTOT * KP];
__device__ uint32_t g_os[(size_t)MTOT * KP];

// ============================================================
// fp32 -> split bf16 pairs (big + small), packed, permuted.
// ============================================================
__device__ __forceinline__ uint32_t packpair(float x0, float x1, uint32_t& small) {
    __nv_bfloat16 h0 = __float2bfloat16(x0);
    __nv_bfloat16 h1 = __float2bfloat16(x1);
    float r0 = x0 - __bfloat162float(h0);
    float r1 = x1 - __bfloat162float(h1);
    __nv_bfloat16 e0 = __float2bfloat16(r0);
    __nv_bfloat16 e1 = __float2bfloat16(r1);
    small = ((uint32_t)__bfloat16_as_ushort(e1) << 16) | __bfloat16_as_ushort(e0);
    return ((uint32_t)__bfloat16_as_ushort(h1) << 16) | __bfloat16_as_ushort(h0);
}

__global__ __launch_bounds__(256)
void split_bf16(const float* __restrict__ X, uint32_t* __restrict__ Xb,
                uint32_t* __restrict__ Xs, int n4) {
    int i = blockIdx.x * blockDim.x + threadIdx.x;
    if (i >= n4) return;
    float4 v = ((const float4*)X)[i];
    uint32_t s0, s1;
    uint32_t b0 = packpair(v.x, v.y, s0);
    uint32_t b1 = packpair(v.z, v.w, s1);
    const int k = 2 * i;
    const int base = k & ~7;
    const int j0 = k & 7;
    const int p0 = ((j0 & 3) << 1) | (j0 >> 2);
    const int j1 = j0 + 1;
    const int p1 = ((j1 & 3) << 1) | (j1 >> 2);
    Xb[base + p0] = b0; Xb[base + p1] = b1;
    Xs[base + p0] = s0; Xs[base + p1] = s1;
}

// ============================================================
// Split-bf16 GEMM: C = A*B^T, D = AbBb + AbBs + AsBb.
// Block tile 256x128x32, 256 thr, warp tile 64x64 (4x2 warps).
// Per ks-step: 32 LDS.64 feed 96 mma (3:1).
// cp.async double-buffered from pre-permuted globals.
// ============================================================
#define PSTR 20                     // smem row stride in u32
#define A_ARR (256 * PSTR)          // 5120 u32
#define B_ARR (128 * PSTR)          // 2560 u32
#define STG2  (2 * A_ARR + 2 * B_ARR)   // 15360 u32 / stage
#define GSMEM (2 * STG2 * 4)        // 122880 B

__global__ void __launch_bounds__(256)
sgemm_bfx3(const uint32_t* __restrict__ Ab, const uint32_t* __restrict__ As,
           const uint32_t* __restrict__ Bb, const uint32_t* __restrict__ Bs,
           float* __restrict__ C, int M, int N, int Kp) {
    extern __shared__ uint32_t su[];

    const int tid  = threadIdx.x;
    const int w    = tid >> 5;
    const int lane = tid & 31;
    const int g    = lane >> 2;
    const int cg   = lane & 3;
    const int wm   = w >> 1;          // 0..3
    const int wn   = w & 1;           // 0..1
    const int m0 = blockIdx.y * 256;
    const int n0 = blockIdx.x * 128;

    // staging: A row = tid (4 cp16 per array); B row = tid>>1, half = tid&1 (2 per array)
    const uint32_t* pAb = Ab + (size_t)(m0 + tid) * Kp;
    const uint32_t* pAs = As + (size_t)(m0 + tid) * Kp;
    const int brow = tid >> 1;
    const int bh2  = (tid & 1) * 8;
    const uint32_t* pBb = Bb + (size_t)(n0 + brow) * Kp + bh2;
    const uint32_t* pBs = Bs + (size_t)(n0 + brow) * Kp + bh2;
    const uint32_t sbase = smem_u32(su);
    const uint32_t dstA  = sbase + (uint32_t)(tid * PSTR) * 4;
    const uint32_t dstB  = sbase + (uint32_t)(2 * A_ARR + brow * PSTR + bh2) * 4;

    float c[4][8][4];
#pragma unroll
    for (int mi = 0; mi < 4; mi++)
#pragma unroll
        for (int ni = 0; ni < 8; ni++)
#pragma unroll
            for (int i = 0; i < 4; i++) c[mi][ni][i] = 0.f;

    const int nch = Kp / 16;

#define ISSUE(ch, st) do {                                              \
        const int off_ = (ch) * 16;                                     \
        const uint32_t sA_ = dstA + (uint32_t)(st) * (STG2 * 4);        \
        const uint32_t sB_ = dstB + (uint32_t)(st) * (STG2 * 4);        \
        cp16(sA_,      pAb + off_);      cp16(sA_ + 16, pAb + off_ + 4);\
        cp16(sA_ + 32, pAb + off_ + 8);  cp16(sA_ + 48, pAb + off_ + 12);\
        cp16(sA_ + A_ARR * 4,      pAs + off_);                         \
        cp16(sA_ + A_ARR * 4 + 16, pAs + off_ + 4);                     \
        cp16(sA_ + A_ARR * 4 + 32, pAs + off_ + 8);                     \
        cp16(sA_ + A_ARR * 4 + 48, pAs + off_ + 12);                    \
        cp16(sB_,      pBb + off_);      cp16(sB_ + 16, pBb + off_ + 4);\
        cp16(sB_ + B_ARR * 4,      pBs + off_);                         \
        cp16(sB_ + B_ARR * 4 + 16, pBs + off_ + 4);                     \
        CP_COMMIT();                                                    \
    } while (0)

    ISSUE(0, 0);
    ISSUE(1, 1);

    for (int ch = 0; ch < nch; ch++) {
        if (ch + 1 < nch) { CP_WAIT(1); } else { CP_WAIT(0); }
        __syncthreads();

        const uint32_t* SAb = su + (ch & 1) * STG2;
        const uint32_t* SAs = SAb + A_ARR;
        const uint32_t* SBb = SAb + 2 * A_ARR;
        const uint32_t* SBs = SBb + B_ARR;

#pragma unroll
        for (int ks = 0; ks < 2; ks++) {
            uint2 fbb[8], fbs[8];
#pragma unroll
            for (int ni = 0; ni < 8; ni++) {
                const int br = (wn * 64 + ni * 8 + g) * PSTR + ks * 8 + 2 * cg;
                fbb[ni] = *(const uint2*)&SBb[br];
                fbs[ni] = *(const uint2*)&SBs[br];
            }
#pragma unroll
            for (int mi = 0; mi < 4; mi++) {
                const int r = (wm * 64 + mi * 16 + g) * PSTR + ks * 8 + 2 * cg;
                uint2 a0 = *(const uint2*)&SAb[r];
                uint2 a1 = *(const uint2*)&SAb[r + 8 * PSTR];
                uint2 s0 = *(const uint2*)&SAs[r];
                uint2 s1 = *(const uint2*)&SAs[r + 8 * PSTR];
                uint32_t fab[4] = {a0.x, a1.x, a0.y, a1.y};
                uint32_t fas[4] = {s0.x, s1.x, s0.y, s1.y};
#pragma unroll
                for (int ni = 0; ni < 8; ni++) {
                    mma_bf16(c[mi][ni], fab, fbb[ni].x, fbb[ni].y);
                    mma_bf16(c[mi][ni], fab, fbs[ni].x, fbs[ni].y);
                    mma_bf16(c[mi][ni], fas, fbb[ni].x, fbb[ni].y);
                }
            }
        }
        __syncthreads();
        if (ch + 2 < nch) ISSUE(ch + 2, ch & 1);
    }
#undef ISSUE

    // epilogue
#pragma unroll
    for (int mi = 0; mi < 4; mi++) {
        const int r = m0 + wm * 64 + mi * 16 + g;
#pragma unroll
        for (int ni = 0; ni < 8; ni++) {
            const int cc = n0 + wn * 64 + ni * 8 + 2 * cg;
            *(float2*)&C[(size_t)r * N + cc]       = make_float2(c[mi][ni][0], c[mi][ni][1]);
            *(float2*)&C[(size_t)(r + 8) * N + cc] = make_float2(c[mi][ni][2], c[mi][ni][3]);
        }
    }
}

// ============================================================
// rmsnorm + RoPE + head split.  One warp per (b,l,h).
// q pre-scaled by 0.125.  K and V written TF32-ROUNDED
// (bit-identical to the cvt attention used to do at staging).
// V transposed: (b,h,d,l).
// ============================================================
__global__ __launch_bounds__(256)
void norm_rope_split(const float* __restrict__ qkv, const float* __restrict__ rope,
                     const float* __restrict__ qw, const float* __restrict__ kw,
                     float* __restrict__ Q, float* __restrict__ K, float* __restrict__ Vt) {
    const int warp = (blockIdx.x * blockDim.x + threadIdx.x) >> 5;
    const int lane = threadIdx.x & 31;
    const int h  = warp & (HH - 1);
    const int bl = warp >> 4;               // b*L + l
    const int l  = bl & (LL - 1);
    const int b  = bl >> 11;

    const float* base = qkv + (size_t)bl * (3 * DD);
    const float c = rope[l * DH + lane * 2];
    const float s = rope[l * DH + lane * 2 + 1];
    const size_t obase = ((size_t)(b * HH + h) * LL + l) * DH;

    // ---- Q ----
    {
        float2 x = *(const float2*)(base + h * DH + lane * 2);
        float ss = x.x * x.x + x.y * x.y;
#pragma unroll
        for (int o = 16; o; o >>= 1) ss += __shfl_xor_sync(0xffffffffu, ss, o);
        float inv = rsqrtf(ss * (1.f / DH) + 1e-6f);
        float e = x.x * inv * qw[lane * 2];
        float o_ = x.y * inv * qw[lane * 2 + 1];
        Q[obase + lane * 2]     = 0.125f * (e * c - o_ * s);
        Q[obase + lane * 2 + 1] = 0.125f * (e * s + o_ * c);
    }
    // ---- K (tf32-rounded) ----
    {
        float2 x = *(const float2*)(base + DD + h * DH + lane * 2);
        float ss = x.x * x.x + x.y * x.y;
#pragma unroll
        for (int o = 16; o; o >>= 1) ss += __shfl_xor_sync(0xffffffffu, ss, o);
        float inv = rsqrtf(ss * (1.f / DH) + 1e-6f);
        float e = x.x * inv * kw[lane * 2];
        float o_ = x.y * inv * kw[lane * 2 + 1];
        K[obase + lane * 2]     = tf32f(e * c - o_ * s);
        K[obase + lane * 2 + 1] = tf32f(e * s + o_ * c);
    }
    // ---- V transposed write (tf32-rounded): Vt[(b,h), d, l] ----
    {
        float2 v = *(const float2*)(base + 2 * DD + h * DH + lane * 2);
        const size_t vb = ((size_t)(b * HH + h) * DH + lane * 2) * LL + l;
        Vt[vb]      = tf32f(v.x);
        Vt[vb + LL] = tf32f(v.y);
    }
}

// ============================================================
// Flash attention, tf32 mma.sync, P-in-registers.
// K/V arrive pre-tf32-rounded -> staging is a pure copy.
// Epilogue fused with split-bf16 (permuted ob/os).
// ============================================================
#define KSTR 66
#define VSTR 68
#define KBUF (64 * KSTR)
#define VBUF (64 * VSTR)
#define KS_OFF 0
#define VS_OFF (2 * KBUF)
#define ATT_SMEM ((2 * KBUF + 2 * VBUF) * 4)   // 68608 B

__global__ __launch_bounds__(256)
void attn_mma(const float* __restrict__ Qg, const float* __restrict__ Kg,
              const float* __restrict__ Vt,
              uint32_t* __restrict__ Ob, uint32_t* __restrict__ Os) {
    extern __shared__ float sm[];

    const int tid  = threadIdx.x;
    const int w    = tid >> 5;
    const int lane = tid & 31;
    const int g    = lane >> 2;
    const int cg   = lane & 3;
    const int bh   = blockIdx.y;
    const int q0   = blockIdx.x * 128;
    const int r0   = w * 16 + g;

    const int sr = tid >> 2;
    const int sc = (tid & 3) * 16;
    const float* kbase = Kg + ((size_t)bh * LL + sr) * DH + sc;
    const float* vbase = Vt + ((size_t)bh * DH + sr) * LL + sc;

    const float* qbase = Qg + ((size_t)bh * LL + q0) * DH;
    uint32_t qa[8][4];
#pragma unroll
    for (int kt = 0; kt < 8; kt++) {
        qa[kt][0] = tf32bits(qbase[(size_t)r0 * DH + kt * 8 + cg]);
        qa[kt][1] = tf32bits(qbase[(size_t)(r0 + 8) * DH + kt * 8 + cg]);
        qa[kt][2] = tf32bits(qbase[(size_t)r0 * DH + kt * 8 + cg + 4]);
        qa[kt][3] = tf32bits(qbase[(size_t)(r0 + 8) * DH + kt * 8 + cg + 4]);
    }

    float o[8][4];
#pragma unroll
    for (int dt = 0; dt < 8; dt++)
#pragma unroll
        for (int i = 0; i < 4; i++) o[dt][i] = 0.f;
    float m0 = -1e30f, m1 = -1e30f, l0 = 0.f, l1 = 0.f;

    float4 kr[4], vr[4];
#pragma unroll
    for (int q = 0; q < 4; q++) {
        kr[q] = *(const float4*)(kbase + q * 4);
        vr[q] = *(const float4*)(vbase + q * 4);
    }

    for (int kvt = 0; kvt < LL / 64; kvt++) {
        const int buf = kvt & 1;
        float* Ks = sm + KS_OFF + buf * KBUF;
        float* Vs = sm + VS_OFF + buf * VBUF;

        {
            float* krow = &Ks[sr * KSTR];
            float* vrow = &Vs[sr * VSTR];
#pragma unroll
            for (int q = 0; q < 4; q++) {
                int d0 = sc + q * 4;
                float* kd = krow + (d0 & ~7) + ((d0 >> 2) & 1);
                kd[0] = kr[q].x; kd[2] = kr[q].y;
                kd[4] = kr[q].z; kd[6] = kr[q].w;
                *(float4*)(vrow + d0) = vr[q];
            }
        }

        if (kvt + 1 < LL / 64) {
#pragma unroll
            for (int q = 0; q < 4; q++) {
                kr[q] = *(const float4*)(kbase + (size_t)(kvt + 1) * 64 * DH + q * 4);
                vr[q] = *(const float4*)(vbase + (kvt + 1) * 64 + q * 4);
            }
        }

        __syncthreads();

        float s[8][4];
#pragma unroll
        for (int nt = 0; nt < 8; nt++)
#pragma unroll
            for (int i = 0; i < 4; i++) s[nt][i] = 0.f;
#pragma unroll
        for (int kt = 0; kt < 8; kt++) {
#pragma unroll
            for (int nt = 0; nt < 8; nt++) {
                uint2 b = *(const uint2*)&Ks[(nt * 8 + g) * KSTR + kt * 8 + 2 * cg];
                mma_tf32(s[nt], qa[kt], b.x, b.y);
            }
        }

        float mt0 = -1e30f, mt1 = -1e30f;
#pragma unroll
        for (int nt = 0; nt < 8; nt++) {
            mt0 = fmaxf(mt0, fmaxf(s[nt][0], s[nt][1]));
            mt1 = fmaxf(mt1, fmaxf(s[nt][2], s[nt][3]));
        }
        mt0 = fmaxf(mt0, __shfl_xor_sync(0xffffffffu, mt0, 1));
        mt0 = fmaxf(mt0, __shfl_xor_sync(0xffffffffu, mt0, 2));
        mt1 = fmaxf(mt1, __shfl_xor_sync(0xffffffffu, mt1, 1));
        mt1 = fmaxf(mt1, __shfl_xor_sync(0xffffffffu, mt1, 2));

        const float mn0 = fmaxf(m0, mt0);
        const float mn1 = fmaxf(m1, mt1);
        const float a0 = __expf(m0 - mn0);
        const float a1 = __expf(m1 - mn1);
        l0 *= a0; l1 *= a1;
#pragma unroll
        for (int dt = 0; dt < 8; dt++) {
            o[dt][0] *= a0; o[dt][1] *= a0;
            o[dt][2] *= a1; o[dt][3] *= a1;
        }

        uint32_t pa[8][4];
        float ps0 = 0.f, ps1 = 0.f;
#pragma unroll
        for (int nt = 0; nt < 8; nt++) {
            float p00 = __expf(s[nt][0] - mn0);
            float p01 = __expf(s[nt][1] - mn0);
            float p10 = __expf(s[nt][2] - mn1);
            float p11 = __expf(s[nt][3] - mn1);
            ps0 += p00 + p01;
            ps1 += p10 + p11;
            pa[nt][0] = tf32bits(p00);
            pa[nt][1] = tf32bits(p10);
            pa[nt][2] = tf32bits(p01);
            pa[nt][3] = tf32bits(p11);
        }
        ps0 += __shfl_xor_sync(0xffffffffu, ps0, 1);
        ps0 += __shfl_xor_sync(0xffffffffu, ps0, 2);
        ps1 += __shfl_xor_sync(0xffffffffu, ps1, 1);
        ps1 += __shfl_xor_sync(0xffffffffu, ps1, 2);
        l0 += ps0; l1 += ps1;
        m0 = mn0; m1 = mn1;

#pragma unroll
        for (int kt = 0; kt < 8; kt++) {
#pragma unroll
            for (int dt = 0; dt < 8; dt++) {
                uint2 b = *(const uint2*)&Vs[(dt * 8 + g) * VSTR + kt * 8 + 2 * cg];
                mma_tf32(o[dt], pa[kt], b.x, b.y);
            }
        }
    }

    // --- fused epilogue: divide by l, split to bf16 pairs, permuted store ---
    const float il0 = 1.f / l0;
    const float il1 = 1.f / l1;
    const int b = bh >> 4, h = bh & (HH - 1);
    const size_t rowA = (size_t)(b * LL + q0 + r0);
#pragma unroll
    for (int dt = 0; dt < 8; dt++) {
        const int kp_ = h * 32 + dt * 4 + cg;
        const int jj = kp_ & 7;
        const int col = (kp_ & ~7) + (((jj & 3) << 1) | (jj >> 2));
        uint32_t sbits, bbits;
        bbits = packpair(o[dt][0] * il0, o[dt][1] * il0, sbits);
        Ob[rowA * KP + col] = bbits;
        Os[rowA * KP + col] = sbits;
        bbits = packpair(o[dt][2] * il1, o[dt][3] * il1, sbits);
        Ob[(rowA + 8) * KP + col] = bbits;
        Os[(rowA + 8) * KP + col] = sbits;
    }
}

// ============================================================
extern "C" void kernel_launch(void* const* d_in, const int* in_sizes, int n_in,
                              void* d_out, int out_size) {
    const float* x      = (const float*)d_in[0];
    const float* rope   = (const float*)d_in[1];
    const float* w_qkv  = (const float*)d_in[2];
    const float* w_proj = (const float*)d_in[3];
    const float* qw     = (const float*)d_in[4];
    const float* kw     = (const float*)d_in[5];
    float* out = (float*)d_out;

    float *qkv, *Q, *K, *V;
    uint32_t *xb, *xs, *wqb, *wqs, *wpb, *wps, *ob, *os;
    cudaGetSymbolAddress((void**)&qkv, g_qkv);
    cudaGetSymbolAddress((void**)&Q, g_q);
    cudaGetSymbolAddress((void**)&K, g_k);
    cudaGetSymbolAddress((void**)&V, g_v);
    cudaGetSymbolAddress((void**)&xb, g_xb);
    cudaGetSymbolAddress((void**)&xs, g_xs);
    cudaGetSymbolAddress((void**)&wqb, g_wqb);
    cudaGetSymbolAddress((void**)&wqs, g_wqs);
    cudaGetSymbolAddress((void**)&wpb, g_wpb);
    cudaGetSymbolAddress((void**)&wps, g_wps);
    cudaGetSymbolAddress((void**)&ob, g_ob);
    cudaGetSymbolAddress((void**)&os, g_os);

    cudaFuncSetAttribute(attn_mma, cudaFuncAttributeMaxDynamicSharedMemorySize, ATT_SMEM);
    cudaFuncSetAttribute(sgemm_bfx3, cudaFuncAttributeMaxDynamicSharedMemorySize, GSMEM);

    // 0) split fp32 -> permuted bf16 big/small pair arrays
    const int n4x = MTOT * DD / 4;
    const int n4q = 3 * DD * DD / 4;
    const int n4p = DD * DD / 4;
    split_bf16<<<(n4x + 255) / 256, 256>>>(x, xb, xs, n4x);
    split_bf16<<<(n4q + 255) / 256, 256>>>(w_qkv, wqb, wqs, n4q);
    split_bf16<<<(n4p + 255) / 256, 256>>>(w_proj, wpb, wps, n4p);

    // 1) qkv = x @ w_qkv^T   [bf16x3, 256x128 tile, 64x64 warp tile]
    sgemm_bfx3<<<dim3(3 * DD / 128, MTOT / 256), 256, GSMEM>>>(xb, xs, wqb, wqs, qkv, MTOT, 3 * DD, KP);

    // 2) rmsnorm + rope + head split (K/V tf32-pre-rounded)
    norm_rope_split<<<(MTOT * HH) / 8, 256>>>(qkv, rope, qw, kw, Q, K, V);

    // 3) attention -> fused split epilogue writes ob/os directly
    attn_mma<<<dim3(LL / 128, BB * HH), 256, ATT_SMEM>>>(Q, K, V, ob, os);

    // 4) out = O @ w_proj^T  [bf16x3]
    sgemm_bfx3<<<dim3(DD / 128, MTOT / 256), 256, GSMEM>>>(ob, os, wpb, wps, out, MTOT, DD, KP);
}